// round 6
// baseline (speedup 1.0000x reference)
#include <cuda_runtime.h>

#define PAD_ID    100000
#define ITEM_ROWS 100001
#define D   64
#define NB  4096
#define L   200
#define NEGW 0.1f

#define NB_G1   296            // item Gram blocks
#define NB_GV   32             // user Gram blocks
#define NB_GRAM (NB_G1 + NB_GV)   // 328
#define NB_POS  1024           // pos-loss blocks
#define B_PER_BLK 4
#define CHUNK   64
#define GRID_TOTAL (NB_GRAM + NB_POS)   // 1352

// zero-initialized at module load; last block resets them each run
__device__ float g_g1[D * D];
__device__ float g_gv[D * D];
__device__ float g_pos;
__device__ unsigned int g_done;

__device__ __forceinline__ float dot8(float4 a0, float4 a1, float4 b0, float4 b1) {
    float s = a0.x * b0.x;
    s = fmaf(a0.y, b0.y, s);
    s = fmaf(a0.z, b0.z, s);
    s = fmaf(a0.w, b0.w, s);
    s = fmaf(a1.x, b1.x, s);
    s = fmaf(a1.y, b1.y, s);
    s = fmaf(a1.z, b1.z, s);
    s = fmaf(a1.w, b1.w, s);
    return s;
}

__global__ __launch_bounds__(256, 5) void enmf_kernel(
    const int* __restrict__ uids, const int* __restrict__ pos_iids,
    const float* __restrict__ userW, const float* __restrict__ itemW,
    const float* __restrict__ h, float* __restrict__ out)
{
    __shared__ float sm[CHUNK * D];   // 16 KB, reused by all paths
    __shared__ float hh[D];
    __shared__ float warpsum[8];
    __shared__ unsigned int s_rank;

    const int tid = threadIdx.x;
    const int bid = blockIdx.x;
    if (tid < D) hh[tid] = h[tid];
    __syncthreads();

    // ---- interleave block types so FMA-bound and L2-bound blocks co-reside ----
    int gram_id = -1, pos_id = -1;
    if (bid < NB_GRAM * 4) {
        if ((bid & 3) == 3) gram_id = bid >> 2;
        else                pos_id  = (bid >> 2) * 3 + (bid & 3);
    } else {
        pos_id = NB_GRAM * 3 + (bid - NB_GRAM * 4);
    }

    if (gram_id >= 0) {
        // ================= Gram path (upper triangle only) =================
        const bool is_item   = (gram_id < NB_G1);
        const int rows_total = is_item ? ITEM_ROWS : NB;
        const int nblk       = is_item ? NB_G1 : NB_GV;
        const int gb         = is_item ? gram_id : gram_id - NB_G1;
        const int per        = (rows_total + nblk - 1) / nblk;
        const int r0         = gb * per;
        const int r1         = min(r0 + per, rows_total);

        // map tid -> upper-triangle 4x4 tile (ti <= tj) of the 16x16 tile grid
        const bool active = (tid < 136);
        int ti = 0, tj = 0;
        if (active) {
            int tt = tid;
            while (tt >= 16 - ti) { tt -= 16 - ti; ti++; }
            tj = ti + tt;
        }

        float c[4][4];
        #pragma unroll
        for (int i = 0; i < 4; i++)
            #pragma unroll
            for (int j = 0; j < 4; j++) c[i][j] = 0.f;

        float4* smv = (float4*)sm;
        const float4* hv4 = (const float4*)hh;

        for (int base = r0; base < r1; base += CHUNK) {
            for (int i = tid; i < CHUNK * 16; i += 256) {
                int r = base + (i >> 4);
                float4 v = make_float4(0.f, 0.f, 0.f, 0.f);
                if (r < r1) {
                    if (is_item) {
                        v = ((const float4*)itemW)[(size_t)r * 16 + (i & 15)];
                    } else {
                        float4 u = ((const float4*)userW)[(size_t)uids[r] * 16 + (i & 15)];
                        float4 hx = hv4[i & 15];
                        v = make_float4(u.x * hx.x, u.y * hx.y, u.z * hx.z, u.w * hx.w);
                    }
                }
                smv[i] = v;
            }
            __syncthreads();

            if (active) {
                #pragma unroll 8
                for (int r = 0; r < CHUNK; r++) {
                    float4 a = smv[r * 16 + ti];
                    float4 b = smv[r * 16 + tj];
                    float av[4] = {a.x, a.y, a.z, a.w};
                    float bv[4] = {b.x, b.y, b.z, b.w};
                    #pragma unroll
                    for (int i = 0; i < 4; i++)
                        #pragma unroll
                        for (int j = 0; j < 4; j++)
                            c[i][j] = fmaf(av[i], bv[j], c[i][j]);
                }
            }
            __syncthreads();
        }

        if (active) {
            float* dst = is_item ? g_g1 : g_gv;
            #pragma unroll
            for (int i = 0; i < 4; i++)
                #pragma unroll
                for (int j = 0; j < 4; j++) {
                    if (!(ti == tj && j < i))   // store strict upper triangle only
                        atomicAdd(&dst[(ti * 4 + i) * D + (tj * 4 + j)], c[i][j]);
                }
        }
    } else {
        // ===== pos-loss path: 8 lanes per item row, 4 rows/warp, 3-shfl reduce =====
        const int b0 = pos_id * B_PER_BLK;

        for (int i = tid; i < B_PER_BLK * D; i += 256) {
            int bl = i >> 6, d = i & 63;
            sm[i] = userW[(size_t)uids[b0 + bl] * D + d] * hh[d];
        }
        __syncthreads();

        const int warp = tid >> 5, lane = tid & 31;
        const int g    = lane >> 3;     // row group 0..3 within warp
        const int sub  = lane & 7;      // 8 lanes per row
        float acc = 0.f;

        for (int bl = 0; bl < B_PER_BLK; bl++) {
            // this lane's 8-dim slice of v_b: two float4s (row split in 128B halves)
            const float4* vrow = (const float4*)(sm + bl * D);
            float4 va = vrow[sub];
            float4 vb = vrow[8 + sub];
            const int* pi = pos_iids + (size_t)(b0 + bl) * L;

            // each warp handles 8 rows (2 index quads) per step; 8 warps cover 64
            for (int l0 = warp * 8; l0 < L; l0 += 64) {
                int4 ida = ((const int4*)pi)[(l0 >> 2)];
                int4 idb = ((const int4*)pi)[(l0 >> 2) + 1];
                int ia = (g == 0) ? ida.x : (g == 1) ? ida.y : (g == 2) ? ida.z : ida.w;
                int ib = (g == 0) ? idb.x : (g == 1) ? idb.y : (g == 2) ? idb.z : idb.w;

                float pa = 0.f, pb = 0.f;
                if (ia != PAD_ID) {
                    const float4* r = (const float4*)(itemW + (size_t)ia * D);
                    pa = dot8(r[sub], r[8 + sub], va, vb);
                }
                if (ib != PAD_ID) {
                    const float4* r = (const float4*)(itemW + (size_t)ib * D);
                    pb = dot8(r[sub], r[8 + sub], va, vb);
                }
                // 3-level butterfly within each 8-lane group (all 4 rows in parallel)
                #pragma unroll
                for (int o = 4; o > 0; o >>= 1) {
                    pa += __shfl_xor_sync(0xffffffffu, pa, o);
                    pb += __shfl_xor_sync(0xffffffffu, pb, o);
                }
                if (sub == 0)
                    acc += (1.0f - NEGW) * (pa * pa + pb * pb) - 2.0f * (pa + pb);
            }
        }

        // acc is nonzero only on sub==0 lanes; one butterfly sums the warp
        #pragma unroll
        for (int o = 16; o > 0; o >>= 1)
            acc += __shfl_xor_sync(0xffffffffu, acc, o);
        if (lane == 0) warpsum[warp] = acc;
        __syncthreads();
        if (tid == 0) {
            float s = 0.f;
            #pragma unroll
            for (int w = 0; w < 8; w++) s += warpsum[w];
            atomicAdd(&g_pos, s);
        }
    }

    // ================= last block combines + resets =================
    __threadfence();
    __syncthreads();
    if (tid == 0) s_rank = atomicAdd(&g_done, 1u);
    __syncthreads();

    if (s_rank == GRID_TOTAL - 1) {
        volatile float* v1 = g_g1;
        volatile float* v2 = g_gv;
        float s = 0.f;
        for (int e = tid; e < D * D; e += 256) {
            int i = e >> 6, j = e & 63;
            float w = (i == j) ? 1.f : 2.f;     // mirror the strict upper triangle
            s += w * v1[e] * v2[e];
        }
        sm[tid] = s;
        __syncthreads();
        for (int off = 128; off > 0; off >>= 1) {
            if (tid < off) sm[tid] += sm[tid + off];
            __syncthreads();
        }
        if (tid == 0) {
            out[0] = NEGW * sm[0] + *(volatile float*)&g_pos;
            g_pos = 0.f;
            g_done = 0u;
        }
        for (int e = tid; e < D * D; e += 256) { g_g1[e] = 0.f; g_gv[e] = 0.f; }
    }
}

extern "C" void kernel_launch(void* const* d_in, const int* in_sizes, int n_in,
                              void* d_out, int out_size) {
    const int*   uids     = (const int*)d_in[0];
    const int*   pos_iids = (const int*)d_in[1];
    const float* userW    = (const float*)d_in[2];
    const float* itemW    = (const float*)d_in[3];
    const float* h        = (const float*)d_in[4];
    float* out = (float*)d_out;

    enmf_kernel<<<GRID_TOTAL, 256>>>(uids, pos_iids, userW, itemW, h, out);
}

// round 7
// speedup vs baseline: 1.3626x; 1.3626x over previous
#include <cuda_runtime.h>

#define PAD_ID    100000
#define ITEM_ROWS 100001
#define D   64
#define NB  4096
#define L   200
#define NEGW 0.1f

#define NB_G1   296            // item Gram blocks
#define NB_GV   32             // user Gram blocks
#define NB_GRAM (NB_G1 + NB_GV)   // 328
#define NB_POS  1024           // pos-loss blocks
#define B_PER_BLK 4
#define CHUNK   64
#define GRID_TOTAL (NB_GRAM + NB_POS)   // 1352

// zero-initialized at module load; last block resets them each run
__device__ float g_g1[D * D];
__device__ float g_gv[D * D];
__device__ float g_pos;
__device__ unsigned int g_done;

__global__ __launch_bounds__(256) void enmf_kernel(
    const int* __restrict__ uids, const int* __restrict__ pos_iids,
    const float* __restrict__ userW, const float* __restrict__ itemW,
    const float* __restrict__ h, float* __restrict__ out)
{
    __shared__ float sm[CHUNK * D];   // 16 KB, reused by all paths
    __shared__ float hh[D];
    __shared__ float warpsum[8];
    __shared__ unsigned int s_rank;

    const int tid = threadIdx.x;
    const int bid = blockIdx.x;
    if (tid < D) hh[tid] = h[tid];
    __syncthreads();

    // ---- interleave block types so FMA-bound and L2-bound blocks co-reside ----
    int gram_id = -1, pos_id = -1;
    if (bid < NB_GRAM * 4) {
        if ((bid & 3) == 3) gram_id = bid >> 2;
        else                pos_id  = (bid >> 2) * 3 + (bid & 3);
    } else {
        pos_id = NB_GRAM * 3 + (bid - NB_GRAM * 4);
    }

    if (gram_id >= 0) {
        // ================= Gram path (upper triangle only) =================
        const bool is_item   = (gram_id < NB_G1);
        const int rows_total = is_item ? ITEM_ROWS : NB;
        const int nblk       = is_item ? NB_G1 : NB_GV;
        const int gb         = is_item ? gram_id : gram_id - NB_G1;
        const int per        = (rows_total + nblk - 1) / nblk;
        const int r0         = gb * per;
        const int r1         = min(r0 + per, rows_total);

        // map tid -> upper-triangle 4x4 tile (ti <= tj) of the 16x16 tile grid
        const bool active = (tid < 136);
        int ti = 0, tj = 0;
        if (active) {
            int tt = tid;
            while (tt >= 16 - ti) { tt -= 16 - ti; ti++; }
            tj = ti + tt;
        }

        float c[4][4];
        #pragma unroll
        for (int i = 0; i < 4; i++)
            #pragma unroll
            for (int j = 0; j < 4; j++) c[i][j] = 0.f;

        float4* smv = (float4*)sm;
        const float4* hv4 = (const float4*)hh;

        for (int base = r0; base < r1; base += CHUNK) {
            for (int i = tid; i < CHUNK * 16; i += 256) {
                int r = base + (i >> 4);
                float4 v = make_float4(0.f, 0.f, 0.f, 0.f);
                if (r < r1) {
                    if (is_item) {
                        v = ((const float4*)itemW)[(size_t)r * 16 + (i & 15)];
                    } else {
                        float4 u = ((const float4*)userW)[(size_t)uids[r] * 16 + (i & 15)];
                        float4 hx = hv4[i & 15];
                        v = make_float4(u.x * hx.x, u.y * hx.y, u.z * hx.z, u.w * hx.w);
                    }
                }
                smv[i] = v;
            }
            __syncthreads();

            if (active) {
                #pragma unroll 8
                for (int r = 0; r < CHUNK; r++) {
                    float4 a = smv[r * 16 + ti];
                    float4 b = smv[r * 16 + tj];
                    float av[4] = {a.x, a.y, a.z, a.w};
                    float bv[4] = {b.x, b.y, b.z, b.w};
                    #pragma unroll
                    for (int i = 0; i < 4; i++)
                        #pragma unroll
                        for (int j = 0; j < 4; j++)
                            c[i][j] = fmaf(av[i], bv[j], c[i][j]);
                }
            }
            __syncthreads();
        }

        if (active) {
            float* dst = is_item ? g_g1 : g_gv;
            #pragma unroll
            for (int i = 0; i < 4; i++)
                #pragma unroll
                for (int j = 0; j < 4; j++) {
                    if (!(ti == tj && j < i))   // store strict upper triangle only
                        atomicAdd(&dst[(ti * 4 + i) * D + (tj * 4 + j)], c[i][j]);
                }
        }
    } else {
        // ======= pos-loss path: two b-rows per iteration, 8 gathers in flight =======
        const int b0 = pos_id * B_PER_BLK;

        for (int i = tid; i < B_PER_BLK * D; i += 256) {
            int bl = i >> 6, d = i & 63;
            sm[i] = userW[(size_t)uids[b0 + bl] * D + d] * hh[d];
        }
        __syncthreads();

        const int warp = tid >> 5, lane = tid & 31;
        float acc = 0.f;

        for (int blp = 0; blp < B_PER_BLK; blp += 2) {
            float2 vA = ((const float2*)(sm + blp * D))[lane];
            float2 vB = ((const float2*)(sm + (blp + 1) * D))[lane];
            const int* piA = pos_iids + (size_t)(b0 + blp) * L;
            const int* piB = pos_iids + (size_t)(b0 + blp + 1) * L;

            for (int l = warp * 4; l < L; l += 32) {
                int4 iA = ((const int4*)piA)[l >> 2];
                int4 iB = ((const int4*)piB)[l >> 2];

                // 8 independent gathers issued before any reduction
                float2 rA0 = make_float2(0.f, 0.f), rA1 = rA0, rA2 = rA0, rA3 = rA0;
                float2 rB0 = rA0, rB1 = rA0, rB2 = rA0, rB3 = rA0;
                if (iA.x != PAD_ID) rA0 = ((const float2*)(itemW + (size_t)iA.x * D))[lane];
                if (iA.y != PAD_ID) rA1 = ((const float2*)(itemW + (size_t)iA.y * D))[lane];
                if (iA.z != PAD_ID) rA2 = ((const float2*)(itemW + (size_t)iA.z * D))[lane];
                if (iA.w != PAD_ID) rA3 = ((const float2*)(itemW + (size_t)iA.w * D))[lane];
                if (iB.x != PAD_ID) rB0 = ((const float2*)(itemW + (size_t)iB.x * D))[lane];
                if (iB.y != PAD_ID) rB1 = ((const float2*)(itemW + (size_t)iB.y * D))[lane];
                if (iB.z != PAD_ID) rB2 = ((const float2*)(itemW + (size_t)iB.z * D))[lane];
                if (iB.w != PAD_ID) rB3 = ((const float2*)(itemW + (size_t)iB.w * D))[lane];

                float a0 = fmaf(rA0.x, vA.x, rA0.y * vA.y);
                float a1 = fmaf(rA1.x, vA.x, rA1.y * vA.y);
                float a2 = fmaf(rA2.x, vA.x, rA2.y * vA.y);
                float a3 = fmaf(rA3.x, vA.x, rA3.y * vA.y);
                float b0f = fmaf(rB0.x, vB.x, rB0.y * vB.y);
                float b1f = fmaf(rB1.x, vB.x, rB1.y * vB.y);
                float b2f = fmaf(rB2.x, vB.x, rB2.y * vB.y);
                float b3f = fmaf(rB3.x, vB.x, rB3.y * vB.y);

                // two independent 4-wide butterfly trees
                #pragma unroll
                for (int o = 16; o > 0; o >>= 1) {
                    a0  += __shfl_xor_sync(0xffffffffu, a0, o);
                    b0f += __shfl_xor_sync(0xffffffffu, b0f, o);
                    a1  += __shfl_xor_sync(0xffffffffu, a1, o);
                    b1f += __shfl_xor_sync(0xffffffffu, b1f, o);
                    a2  += __shfl_xor_sync(0xffffffffu, a2, o);
                    b2f += __shfl_xor_sync(0xffffffffu, b2f, o);
                    a3  += __shfl_xor_sync(0xffffffffu, a3, o);
                    b3f += __shfl_xor_sync(0xffffffffu, b3f, o);
                }
                float sq = a0 * a0 + a1 * a1 + a2 * a2 + a3 * a3
                         + b0f * b0f + b1f * b1f + b2f * b2f + b3f * b3f;
                float ln = a0 + a1 + a2 + a3 + b0f + b1f + b2f + b3f;
                acc += (1.0f - NEGW) * sq - 2.0f * ln;
            }
        }

        // acc identical on all lanes after butterflies — take lane 0 once
        if (lane == 0) warpsum[warp] = acc;
        __syncthreads();
        if (tid == 0) {
            float s = 0.f;
            #pragma unroll
            for (int w = 0; w < 8; w++) s += warpsum[w];
            atomicAdd(&g_pos, s);
        }
    }

    // ================= last block combines + resets =================
    __threadfence();
    __syncthreads();
    if (tid == 0) s_rank = atomicAdd(&g_done, 1u);
    __syncthreads();

    if (s_rank == GRID_TOTAL - 1) {
        volatile float* v1 = g_g1;
        volatile float* v2 = g_gv;
        float s = 0.f;
        for (int e = tid; e < D * D; e += 256) {
            int i = e >> 6, j = e & 63;
            float w = (i == j) ? 1.f : 2.f;     // mirror the strict upper triangle
            s += w * v1[e] * v2[e];
        }
        sm[tid] = s;
        __syncthreads();
        for (int off = 128; off > 0; off >>= 1) {
            if (tid < off) sm[tid] += sm[tid + off];
            __syncthreads();
        }
        if (tid == 0) {
            out[0] = NEGW * sm[0] + *(volatile float*)&g_pos;
            g_pos = 0.f;
            g_done = 0u;
        }
        for (int e = tid; e < D * D; e += 256) { g_g1[e] = 0.f; g_gv[e] = 0.f; }
    }
}

extern "C" void kernel_launch(void* const* d_in, const int* in_sizes, int n_in,
                              void* d_out, int out_size) {
    const int*   uids     = (const int*)d_in[0];
    const int*   pos_iids = (const int*)d_in[1];
    const float* userW    = (const float*)d_in[2];
    const float* itemW    = (const float*)d_in[3];
    const float* h        = (const float*)d_in[4];
    float* out = (float*)d_out;

    enmf_kernel<<<GRID_TOTAL, 256>>>(uids, pos_iids, userW, itemW, h, out);
}